// round 14
// baseline (speedup 1.0000x reference)
#include <cuda_runtime.h>
#include <cuda_bf16.h>
#include <cstdint>
#include <math.h>

#define T_DIM 8192
#define D_DIM 4096
#define E_DIM 64
#define BM    64
#define KC    64
#define NTILES (D_DIM / KC)
#define GAP_TAU 4e-4f
#define NTHREADS 512
#define NSTAGE 4

// smem byte layout
#define OFF_BIAS 0              // 64 floats
#define OFF_VK   512            // 16 warps x 2 floats
#define OFF_STAGE0 1024
#define STAGE_BYTES 32768       // A_raw 16KB + B terms 2x8KB
#define STAGE_A 0               // A_raw fp32, slot-linear (slot*16)
#define STAGE_B 16384           // B: term t at +t*8192, swizzled rows
#define OFF_ATERM (OFF_STAGE0 + NSTAGE * STAGE_BYTES)   // 132096
#define ATERM_BYTES 16384       // 2 terms x 8KB, one per parity
#define SMEM_BYTES (OFF_ATERM + 2 * ATERM_BYTES)        // 164864
// epilogue union (overlays stage region)
#define OFF_L OFF_STAGE0
#define OFF_S (OFF_STAGE0 + 16384)

// W split into 2 bf16 terms (round-to-nearest), [term][e*4096+k]
__device__ __align__(16) unsigned short g_Bsplit[2][E_DIM * D_DIM];

// ---------------------------------------------------------------------------
// helpers
// ---------------------------------------------------------------------------
__device__ __forceinline__ uint32_t smem_u32(const void* p) {
    uint32_t a;
    asm("{ .reg .u64 t; cvta.to.shared.u64 t, %1; cvt.u32.u64 %0, t; }"
        : "=r"(a) : "l"(p));
    return a;
}
__device__ __forceinline__ void cp_async16(uint32_t dst, const void* src) {
    asm volatile("cp.async.cg.shared.global [%0], [%1], 16;"
                 :: "r"(dst), "l"(src));
}
__device__ __forceinline__ void cp_commit() {
    asm volatile("cp.async.commit_group;" ::: "memory");
}
__device__ __forceinline__ void cp_wait2() {
    asm volatile("cp.async.wait_group 2;" ::: "memory");
}
__device__ __forceinline__ void ldsm_x4(uint32_t* r, uint32_t addr) {
    asm volatile("ldmatrix.sync.aligned.m8n8.x4.shared.b16 {%0,%1,%2,%3}, [%4];"
                 : "=r"(r[0]), "=r"(r[1]), "=r"(r[2]), "=r"(r[3]) : "r"(addr));
}
__device__ __forceinline__ void mma_bf16(float* c, const uint32_t* a,
                                         uint32_t b0, uint32_t b1) {
    asm volatile(
        "mma.sync.aligned.m16n8k16.row.col.f32.bf16.bf16.f32 "
        "{%0,%1,%2,%3}, {%4,%5,%6,%7}, {%8,%9}, {%0,%1,%2,%3};"
        : "+f"(c[0]), "+f"(c[1]), "+f"(c[2]), "+f"(c[3])
        : "r"(a[0]), "r"(a[1]), "r"(a[2]), "r"(a[3]), "r"(b0), "r"(b1));
}
// packed rn conversion: result.lo = bf16(x), result.hi = bf16(y)
__device__ __forceinline__ uint32_t cvt_bf16x2_rn(float x, float y) {
    uint32_t r;
    asm("cvt.rn.bf16x2.f32 %0, %1, %2;" : "=r"(r) : "f"(y), "f"(x));
    return r;
}

// ---------------------------------------------------------------------------
// Pre-split W into 2 bf16 terms (round-to-nearest)
// ---------------------------------------------------------------------------
__global__ void bsplit_kernel(const float* __restrict__ W) {
    int idx = blockIdx.x * blockDim.x + threadIdx.x;
    if (idx >= E_DIM * D_DIM) return;
    float x = W[idx];
    __nv_bfloat16 t0 = __float2bfloat16(x);
    float r = x - __bfloat162float(t0);
    __nv_bfloat16 t1 = __float2bfloat16(r);
    g_Bsplit[0][idx] = *reinterpret_cast<unsigned short*>(&t0);
    g_Bsplit[1][idx] = *reinterpret_cast<unsigned short*>(&t1);
}

// ---------------------------------------------------------------------------
// JAX threefry2x32, key=(0,42), partitionable counters; bits = o0^o1
// ---------------------------------------------------------------------------
__device__ __forceinline__ uint32_t rotl32(uint32_t x, int d) {
    return (x << d) | (x >> (32 - d));
}
__device__ __forceinline__ uint32_t threefry_bits(uint32_t j) {
    uint32_t x0 = 0u, x1 = j;
    const uint32_t k0 = 0u, k1 = 42u, k2 = 0u ^ 42u ^ 0x1BD11BDAu;
    x0 += k0; x1 += k1;
#define TF_RND(r) { x0 += x1; x1 = rotl32(x1, (r)); x1 ^= x0; }
    TF_RND(13) TF_RND(15) TF_RND(26) TF_RND(6)
    x0 += k1; x1 += k2 + 1u;
    TF_RND(17) TF_RND(29) TF_RND(16) TF_RND(24)
    x0 += k2; x1 += k0 + 2u;
    TF_RND(13) TF_RND(15) TF_RND(26) TF_RND(6)
    x0 += k0; x1 += k1 + 3u;
    TF_RND(17) TF_RND(29) TF_RND(16) TF_RND(24)
    x0 += k1; x1 += k2 + 4u;
    TF_RND(13) TF_RND(15) TF_RND(26) TF_RND(6)
    x0 += k2; x1 += k0 + 5u;
#undef TF_RND
    return x0 ^ x1;
}
__device__ __forceinline__ float bits_to_unif(uint32_t bits) {
    float f = __uint_as_float((bits >> 9) | 0x3F800000u) - 1.0f;
    const float minv = 1e-6f, maxv = 1.0f - 1e-6f;
    float v = __fadd_rn(__fmul_rn(f, maxv - minv), minv);
    return fmaxf(minv, v);
}

// ---------------------------------------------------------------------------
// Fused kernel: cp.async 4-stage pipeline + bf16x2 mma GEMM + bias +
// softmax + Gumbel top-k, with exact-fp32 fallback on knife-edge rows.
// grid = 128 CTAs (BM=64 rows), 512 threads (16 warps: 4 M-grp x 4 N-grp)
// ---------------------------------------------------------------------------
__global__ __launch_bounds__(NTHREADS, 1) void router_mma_kernel(
    const float* __restrict__ A,      // h [T, D]
    const float* __restrict__ Wfull,  // W [64, D] fp32
    const float* __restrict__ bias,   // [64]
    const int*  __restrict__ kptr,
    float* __restrict__ out_mask,
    float* __restrict__ out_weight,
    float* __restrict__ out_logits)
{
    extern __shared__ __align__(1024) char sm[];
    const uint32_t sbase = smem_u32(sm);
    const int tid  = threadIdx.x;
    const int wid  = tid >> 5;       // 0..15
    const int lane = tid & 31;
    const int bm   = blockIdx.x * BM;
    const int mg   = wid >> 2;       // 0..3: rows 16*mg..
    const int ng   = wid & 3;        // 0..3: cols 16*ng..

    if (tid < 64) ((float*)(sm + OFF_BIAS))[tid] = bias[tid];

    // ---- load-slot precompute ----
    // A: 64 rows x 16 16B-chunks = 1024 slots, 2/thread; staged slot-linear.
    const float* agsrc[2];
    uint32_t asts[2];
#pragma unroll
    for (int i = 0; i < 2; i++) {
        int slot = tid + i * NTHREADS;
        int r = slot >> 4, c8 = slot & 15;
        agsrc[i] = A + (size_t)(bm + r) * D_DIM + c8 * 4;
        // A-term store: bf16 row r is 128B; XOR-16B swizzle on 16B chunks
        asts[i] = (uint32_t)(r * 128 + (((c8 >> 1) ^ (r & 7)) << 4) + (c8 & 1) * 8);
    }
    // B: per term 64 experts x 8 16B-chunks = 512 slots; 1/thread/term
    const uint4* bgsrc[2];
    uint32_t bdst[2];
    {
        int e = tid >> 3, ck = tid & 7;
#pragma unroll
        for (int t = 0; t < 2; t++) {
            bgsrc[t] = (const uint4*)((const char*)g_Bsplit[t] + e * 8192 + ck * 16);
            bdst[t] = (uint32_t)(STAGE_B + t * 8192 + e * 128 + ((ck ^ (e & 7)) << 4));
        }
    }

    // ---- fragment smem address bases ----
    const int arow0 = 16 * mg + ((lane >> 3) & 1) * 8 + (lane & 7);
    const int ac16  = lane >> 4;
    const int brow0 = 16 * ng + ((lane >> 4) & 1) * 8 + (lane & 7);
    const int bc16  = (lane >> 3) & 1;

    float acc[2][4];
#pragma unroll
    for (int n = 0; n < 2; n++)
#pragma unroll
        for (int x = 0; x < 4; x++) acc[n][x] = 0.0f;

    // ---- prologue: issue tiles 0,1,2 into stages 0,1,2 ----
#pragma unroll
    for (int s = 0; s < NSTAGE - 1; s++) {
        const uint32_t st = sbase + OFF_STAGE0 + s * STAGE_BYTES;
#pragma unroll
        for (int i = 0; i < 2; i++) {
            int slot = tid + i * NTHREADS;
            cp_async16(st + STAGE_A + slot * 16, agsrc[i] + s * KC);
        }
#pragma unroll
        for (int t = 0; t < 2; t++)
            cp_async16(st + bdst[t], bgsrc[t] + s * 8);
        cp_commit();
    }

    for (int kt = 0; kt < NTILES; kt++) {
        const int s = kt & (NSTAGE - 1);
        const uint32_t st = sbase + OFF_STAGE0 + s * STAGE_BYTES;

        cp_wait2();
        __syncthreads();   // tile kt arrived everywhere; stage (kt-1)&3 drained

        // issue tile kt+3 into stage (kt+3)&3 == (kt-1)&3
        if (kt + NSTAGE - 1 < NTILES) {
            const int ft = kt + NSTAGE - 1;
            const uint32_t fst = sbase + OFF_STAGE0 + (ft & (NSTAGE - 1)) * STAGE_BYTES;
#pragma unroll
            for (int i = 0; i < 2; i++) {
                int slot = tid + i * NTHREADS;
                cp_async16(fst + STAGE_A + slot * 16, agsrc[i] + ft * KC);
            }
#pragma unroll
            for (int t = 0; t < 2; t++)
                cp_async16(fst + bdst[t], bgsrc[t] + ft * 8);
        }
        cp_commit();       // uniform group count (empty at tail)

        // ---- convert staged A fp32 -> 2 bf16 terms into Aterm[kt&1] ----
        char* at = sm + OFF_ATERM + (kt & 1) * ATERM_BYTES;
#pragma unroll
        for (int i = 0; i < 2; i++) {
            int slot = tid + i * NTHREADS;
            float4 v = *(const float4*)(sm + OFF_STAGE0 + s * STAGE_BYTES +
                                        STAGE_A + slot * 16);
            uint32_t q0 = cvt_bf16x2_rn(v.x, v.y);
            uint32_t q1 = cvt_bf16x2_rn(v.z, v.w);
            float rx = v.x - __uint_as_float(q0 << 16);
            float ry = v.y - __uint_as_float(q0 & 0xFFFF0000u);
            float rz = v.z - __uint_as_float(q1 << 16);
            float rw = v.w - __uint_as_float(q1 & 0xFFFF0000u);
            uint32_t q2 = cvt_bf16x2_rn(rx, ry);
            uint32_t q3 = cvt_bf16x2_rn(rz, rw);
            *(uint2*)(at + 0 * 8192 + asts[i]) = make_uint2(q0, q1);
            *(uint2*)(at + 1 * 8192 + asts[i]) = make_uint2(q2, q3);
        }
        __syncthreads();   // A terms visible to all warps

        // ---- compute: 4 k16-steps; 4 ldsm + 6 mma per step per warp ----
        const uint32_t atu = sbase + OFF_ATERM + (kt & 1) * ATERM_BYTES;
        const uint32_t btu = st + STAGE_B;
#pragma unroll
        for (int ks = 0; ks < 4; ks++) {
            uint32_t af[2][4];
            uint32_t bf_[2][4];
#pragma unroll
            for (int t = 0; t < 2; t++) {
                {
                    const int c16 = 2 * ks + ac16;
                    ldsm_x4(af[t], atu + t * 8192 + arow0 * 128 +
                                   ((c16 ^ (arow0 & 7)) << 4));
                }
                {
                    const int c16 = 2 * ks + bc16;
                    ldsm_x4(bf_[t], btu + t * 8192 + brow0 * 128 +
                                    ((c16 ^ (brow0 & 7)) << 4));
                }
            }
            const int pa[3] = {0, 0, 1};
            const int pb[3] = {0, 1, 0};
#pragma unroll
            for (int p = 0; p < 3; p++)
#pragma unroll
                for (int ns = 0; ns < 2; ns++)
                    mma_bf16(acc[ns], af[pa[p]],
                             bf_[pb[p]][ns * 2], bf_[pb[p]][ns * 2 + 1]);
        }
    }
    __syncthreads();   // all compute done before overlaying L/S on stages

    // ---- epilogue: bias add, logits to gmem + smem ----
    const float* bias_s = (const float*)(sm + OFF_BIAS);
    float* L = (float*)(sm + OFF_L);
    float* S = (float*)(sm + OFF_S);
    {
        const int g = lane >> 2, tg = lane & 3;
#pragma unroll
        for (int ns = 0; ns < 2; ns++) {
            const int col = 16 * ng + 8 * ns + 2 * tg;
            const float bx = bias_s[col], by = bias_s[col + 1];
#pragma unroll
            for (int half = 0; half < 2; half++) {
                const int row = 16 * mg + g + 8 * half;
                float vx = acc[ns][half * 2 + 0] + bx;
                float vy = acc[ns][half * 2 + 1] + by;
                L[row * 64 + col]     = vx;
                L[row * 64 + col + 1] = vy;
                *(float2*)(out_logits + (size_t)(bm + row) * 64 + col) =
                    make_float2(vx, vy);
            }
        }
    }
    __syncthreads();

    // ---- router: softmax + Gumbel top-k; 16 warps x 4 rows ----
    const int kk = kptr ? *kptr : 8;
    const int ln = lane;
    float* vk = (float*)(sm + OFF_VK) + wid * 2;

    for (int rr = 0; rr < 4; rr++) {
        const int r = wid * 4 + rr;
        const int grow = bm + r;
        const float l0 = L[r * 64 + ln];
        const float l1 = L[r * 64 + ln + 32];

        const uint32_t j0 = (uint32_t)(grow * 64 + ln);
        const float g0 = -logf(-logf(bits_to_unif(threefry_bits(j0))));
        const float g1 = -logf(-logf(bits_to_unif(threefry_bits(j0 + 32u))));
        float sc0 = l0 + g0;
        float sc1 = l1 + g1;
        S[r * 64 + ln]      = sc0;
        S[r * 64 + ln + 32] = sc1;
        __syncwarp();

        float m = fmaxf(l0, l1);
#pragma unroll
        for (int d2 = 16; d2 >= 1; d2 >>= 1)
            m = fmaxf(m, __shfl_xor_sync(0xFFFFFFFFu, m, d2));
        const float e0 = expf(l0 - m);
        const float e1 = expf(l1 - m);
        float z = e0 + e1;
#pragma unroll
        for (int d2 = 16; d2 >= 1; d2 >>= 1)
            z += __shfl_xor_sync(0xFFFFFFFFu, z, d2);
        const float w0 = e0 / z;
        const float w1 = e1 / z;

        int c0 = 0, c1 = 0;
#pragma unroll 16
        for (int i = 0; i < 64; i++) {
            const float v = S[r * 64 + i];
            c0 += (v > sc0) || (v == sc0 && i < ln);
            c1 += (v > sc1) || (v == sc1 && i < ln + 32);
        }

        // ---- knife-edge detection: gap between rank kk-1 and rank kk ----
        if (c0 == kk - 1) vk[0] = sc0;
        if (c1 == kk - 1) vk[0] = sc1;
        if (c0 == kk)     vk[1] = sc0;
        if (c1 == kk)     vk[1] = sc1;
        __syncwarp();
        const bool flagged = (vk[0] - vk[1] < GAP_TAU);   // warp-uniform

        if (flagged) {
            // Recompute this row's logits BIT-IDENTICALLY to the verified
            // fp32 kernel: sequential fma over k ascending, single
            // accumulator, then +bias.
            const float* arow = A + (size_t)grow * D_DIM;
            const float* wp0  = Wfull + (size_t)ln * D_DIM;
            const float* wp1  = Wfull + (size_t)(ln + 32) * D_DIM;
            float p0 = 0.f, p1 = 0.f;
            for (int k4 = 0; k4 < D_DIM; k4 += 4) {
                float4 av = *(const float4*)(arow + k4);
                float4 u0 = *(const float4*)(wp0 + k4);
                float4 u1 = *(const float4*)(wp1 + k4);
                p0 = fmaf(av.x, u0.x, p0); p1 = fmaf(av.x, u1.x, p1);
                p0 = fmaf(av.y, u0.y, p0); p1 = fmaf(av.y, u1.y, p1);
                p0 = fmaf(av.z, u0.z, p0); p1 = fmaf(av.z, u1.z, p1);
                p0 = fmaf(av.w, u0.w, p0); p1 = fmaf(av.w, u1.w, p1);
            }
            sc0 = (p0 + bias_s[ln])      + g0;
            sc1 = (p1 + bias_s[ln + 32]) + g1;
            S[r * 64 + ln]      = sc0;
            S[r * 64 + ln + 32] = sc1;
            __syncwarp();
            c0 = 0; c1 = 0;
#pragma unroll 16
            for (int i = 0; i < 64; i++) {
                const float v = S[r * 64 + i];
                c0 += (v > sc0) || (v == sc0 && i < ln);
                c1 += (v > sc1) || (v == sc1 && i < ln + 32);
            }
        }

        out_mask[j0]         = (c0 < kk) ? 1.0f : 0.0f;
        out_mask[j0 + 32u]   = (c1 < kk) ? 1.0f : 0.0f;
        out_weight[j0]       = w0;
        out_weight[j0 + 32u] = w1;
        __syncwarp();
    }
}

// ---------------------------------------------------------------------------
// Output layout: tuple (mask, weight, logits) concatenated as f32.
// ---------------------------------------------------------------------------
extern "C" void kernel_launch(void* const* d_in, const int* in_sizes, int n_in,
                              void* d_out, int out_size) {
    const float* h    = (const float*)d_in[0];
    const float* W    = (const float*)d_in[1];
    const float* bias = (const float*)d_in[2];
    const int*   kptr = (n_in > 3) ? (const int*)d_in[3] : nullptr;

    float* out        = (float*)d_out;
    float* out_mask   = out;
    float* out_weight = out + (size_t)T_DIM * E_DIM;
    float* out_logits = out + 2 * (size_t)T_DIM * E_DIM;

    cudaFuncSetAttribute(router_mma_kernel,
                         cudaFuncAttributeMaxDynamicSharedMemorySize, SMEM_BYTES);
    bsplit_kernel<<<(E_DIM * D_DIM + 255) / 256, 256>>>(W);
    router_mma_kernel<<<T_DIM / BM, NTHREADS, SMEM_BYTES>>>(h, W, bias, kptr,
                                                            out_mask, out_weight,
                                                            out_logits);
}

// round 15
// speedup vs baseline: 1.0326x; 1.0326x over previous
#include <cuda_runtime.h>
#include <cuda_bf16.h>
#include <cstdint>
#include <math.h>

#define T_DIM 8192
#define D_DIM 4096
#define E_DIM 64
#define BM    32
#define KC    64
#define NTILES (D_DIM / KC)
#define GAP_TAU 4e-4f
#define NTHREADS 256

// smem byte layout
#define OFF_BIAS 0            // 64 floats
#define OFF_VK   512          // 8 warps x 2 floats
#define OFF_BUF  1024
#define A_TERM_BYTES 4096     // 32 rows x 128B
#define B_BASE   8192         // 2*A_TERM_BYTES
#define B_TERM_BYTES 8192     // 64 rows x 128B
#define BUF_BYTES 24576       // 2*4KB + 2*8KB
#define SMEM_BYTES (OFF_BUF + 2 * BUF_BYTES)   // 50176 -> 2 CTAs/SM
// epilogue union (overlays buffers)
#define OFF_L OFF_BUF
#define OFF_S (OFF_BUF + 8192)

// W split into 2 bf16 terms (round-to-nearest), [term][e*4096+k]
__device__ __align__(16) unsigned short g_Bsplit[2][E_DIM * D_DIM];

// ---------------------------------------------------------------------------
// helpers
// ---------------------------------------------------------------------------
__device__ __forceinline__ uint32_t smem_u32(const void* p) {
    uint32_t a;
    asm("{ .reg .u64 t; cvta.to.shared.u64 t, %1; cvt.u32.u64 %0, t; }"
        : "=r"(a) : "l"(p));
    return a;
}
__device__ __forceinline__ void ldsm_x4(uint32_t* r, uint32_t addr) {
    asm volatile("ldmatrix.sync.aligned.m8n8.x4.shared.b16 {%0,%1,%2,%3}, [%4];"
                 : "=r"(r[0]), "=r"(r[1]), "=r"(r[2]), "=r"(r[3]) : "r"(addr));
}
__device__ __forceinline__ void mma_bf16(float* c, const uint32_t* a,
                                         uint32_t b0, uint32_t b1) {
    asm volatile(
        "mma.sync.aligned.m16n8k16.row.col.f32.bf16.bf16.f32 "
        "{%0,%1,%2,%3}, {%4,%5,%6,%7}, {%8,%9}, {%0,%1,%2,%3};"
        : "+f"(c[0]), "+f"(c[1]), "+f"(c[2]), "+f"(c[3])
        : "r"(a[0]), "r"(a[1]), "r"(a[2]), "r"(a[3]), "r"(b0), "r"(b1));
}
// packed rn conversion: result.lo = bf16(x), result.hi = bf16(y)
__device__ __forceinline__ uint32_t cvt_bf16x2_rn(float x, float y) {
    uint32_t r;
    asm("cvt.rn.bf16x2.f32 %0, %1, %2;" : "=r"(r) : "f"(y), "f"(x));
    return r;
}

// ---------------------------------------------------------------------------
// Pre-split W into 2 bf16 terms (round-to-nearest)
// ---------------------------------------------------------------------------
__global__ void bsplit_kernel(const float* __restrict__ W) {
    int idx = blockIdx.x * blockDim.x + threadIdx.x;
    if (idx >= E_DIM * D_DIM) return;
    float x = W[idx];
    __nv_bfloat16 t0 = __float2bfloat16(x);
    float r = x - __bfloat162float(t0);
    __nv_bfloat16 t1 = __float2bfloat16(r);
    g_Bsplit[0][idx] = *reinterpret_cast<unsigned short*>(&t0);
    g_Bsplit[1][idx] = *reinterpret_cast<unsigned short*>(&t1);
}

// ---------------------------------------------------------------------------
// JAX threefry2x32, key=(0,42), partitionable counters; bits = o0^o1
// ---------------------------------------------------------------------------
__device__ __forceinline__ uint32_t rotl32(uint32_t x, int d) {
    return (x << d) | (x >> (32 - d));
}
__device__ __forceinline__ uint32_t threefry_bits(uint32_t j) {
    uint32_t x0 = 0u, x1 = j;
    const uint32_t k0 = 0u, k1 = 42u, k2 = 0u ^ 42u ^ 0x1BD11BDAu;
    x0 += k0; x1 += k1;
#define TF_RND(r) { x0 += x1; x1 = rotl32(x1, (r)); x1 ^= x0; }
    TF_RND(13) TF_RND(15) TF_RND(26) TF_RND(6)
    x0 += k1; x1 += k2 + 1u;
    TF_RND(17) TF_RND(29) TF_RND(16) TF_RND(24)
    x0 += k2; x1 += k0 + 2u;
    TF_RND(13) TF_RND(15) TF_RND(26) TF_RND(6)
    x0 += k0; x1 += k1 + 3u;
    TF_RND(17) TF_RND(29) TF_RND(16) TF_RND(24)
    x0 += k1; x1 += k2 + 4u;
    TF_RND(13) TF_RND(15) TF_RND(26) TF_RND(6)
    x0 += k2; x1 += k0 + 5u;
#undef TF_RND
    return x0 ^ x1;
}
__device__ __forceinline__ float bits_to_unif(uint32_t bits) {
    float f = __uint_as_float((bits >> 9) | 0x3F800000u) - 1.0f;
    const float minv = 1e-6f, maxv = 1.0f - 1e-6f;
    float v = __fadd_rn(__fmul_rn(f, maxv - minv), minv);
    return fmaxf(minv, v);
}

// ---------------------------------------------------------------------------
// Fused kernel: bf16x2 (RN split, 3 products) mma.sync GEMM + bias +
// softmax + Gumbel top-k, with exact-fp32 fallback on knife-edge rows.
// grid = 256 CTAs (BM=32 rows), 256 threads (8 warps: 2 M-grp x 4 N-grp),
// 2 CTAs co-resident per SM so barrier/dependency bubbles of one CTA are
// filled by the other.
// ---------------------------------------------------------------------------
__global__ __launch_bounds__(NTHREADS, 2) void router_mma_kernel(
    const float* __restrict__ A,      // h [T, D]
    const float* __restrict__ Wfull,  // W [64, D] fp32
    const float* __restrict__ bias,   // [64]
    const int*  __restrict__ kptr,
    float* __restrict__ out_mask,
    float* __restrict__ out_weight,
    float* __restrict__ out_logits)
{
    extern __shared__ __align__(1024) char sm[];
    const uint32_t sbase = smem_u32(sm);
    const int tid  = threadIdx.x;
    const int wid  = tid >> 5;       // 0..7
    const int lane = tid & 31;
    const int bm   = blockIdx.x * BM;
    const int mg   = wid >> 2;       // 0..1: rows 16*mg..
    const int ng   = wid & 3;        // 0..3: cols 16*ng..

    if (tid < 64) ((float*)(sm + OFF_BIAS))[tid] = bias[tid];

    // ---- gmem load slots ----
    // A: 32 rows x 16 8B-chunks = 512 slots, 2/thread
    const float* aptr[2];
    uint32_t asts[2];
#pragma unroll
    for (int i = 0; i < 2; i++) {
        int slot = tid + i * NTHREADS;
        int r = slot >> 4, c8 = slot & 15;
        aptr[i] = A + (size_t)(bm + r) * D_DIM + c8 * 4;
        asts[i] = (uint32_t)(r * 128 + (((c8 >> 1) ^ (r & 7)) << 4) + (c8 & 1) * 8);
    }
    // B: per term 64 experts x 8 16B-chunks = 512 slots; 2/thread/term
    const uint4* bptr[2][2];
    uint32_t bsts[2][2];
#pragma unroll
    for (int i = 0; i < 2; i++) {
        int slot = tid + i * NTHREADS;
        int e = slot >> 3, ck = slot & 7;
#pragma unroll
        for (int t = 0; t < 2; t++) {
            bptr[t][i] = (const uint4*)((const char*)g_Bsplit[t] + e * 8192 + ck * 16);
            bsts[t][i] = (uint32_t)(B_BASE + t * B_TERM_BYTES +
                                    e * 128 + ((ck ^ (e & 7)) << 4));
        }
    }

    // ---- fragment smem address bases ----
    const int arow0 = 16 * mg + ((lane >> 3) & 1) * 8 + (lane & 7);
    const int ac16  = lane >> 4;
    const int brow0 = 16 * ng + ((lane >> 4) & 1) * 8 + (lane & 7);
    const int bc16  = (lane >> 3) & 1;

    float acc[2][4];
#pragma unroll
    for (int n = 0; n < 2; n++)
#pragma unroll
        for (int x = 0; x < 4; x++) acc[n][x] = 0.0f;

    // prefetch tile 0
    float4 ar[2];
    uint4  br[2][2];
#pragma unroll
    for (int i = 0; i < 2; i++) ar[i] = *(const float4*)aptr[i];
#pragma unroll
    for (int t = 0; t < 2; t++)
#pragma unroll
        for (int i = 0; i < 2; i++) br[t][i] = bptr[t][i][0];

    for (int kt = 0; kt < NTILES; kt++) {
        char* buf = sm + OFF_BUF + (kt & 1) * BUF_BYTES;
        const uint32_t bufu = sbase + OFF_BUF + (kt & 1) * BUF_BYTES;

        // ---- convert A -> 2 bf16 terms (RN), store swizzled; store B ----
#pragma unroll
        for (int i = 0; i < 2; i++) {
            float4 v = ar[i];
            uint32_t q0 = cvt_bf16x2_rn(v.x, v.y);
            uint32_t q1 = cvt_bf16x2_rn(v.z, v.w);
            float rx = v.x - __uint_as_float(q0 << 16);
            float ry = v.y - __uint_as_float(q0 & 0xFFFF0000u);
            float rz = v.z - __uint_as_float(q1 << 16);
            float rw = v.w - __uint_as_float(q1 & 0xFFFF0000u);
            uint32_t q2 = cvt_bf16x2_rn(rx, ry);
            uint32_t q3 = cvt_bf16x2_rn(rz, rw);
            *(uint2*)(buf + 0 * A_TERM_BYTES + asts[i]) = make_uint2(q0, q1);
            *(uint2*)(buf + 1 * A_TERM_BYTES + asts[i]) = make_uint2(q2, q3);
        }
#pragma unroll
        for (int t = 0; t < 2; t++)
#pragma unroll
            for (int i = 0; i < 2; i++)
                *(uint4*)(buf + bsts[t][i]) = br[t][i];

        __syncthreads();

        // prefetch next tile (A stride = KC floats; B stride = 8 uint4)
        if (kt + 1 < NTILES) {
            const int nk = kt + 1;
#pragma unroll
            for (int i = 0; i < 2; i++) ar[i] = *(const float4*)(aptr[i] + nk * KC);
#pragma unroll
            for (int t = 0; t < 2; t++)
#pragma unroll
                for (int i = 0; i < 2; i++) br[t][i] = bptr[t][i][nk * 8];
        }

        // ---- compute: 4 k16-steps; 4 ldsm + 6 mma per step per warp ----
#pragma unroll
        for (int ks = 0; ks < 4; ks++) {
            uint32_t af[2][4];
            uint32_t bf_[2][4];
#pragma unroll
            for (int t = 0; t < 2; t++) {
                {
                    const int c16 = 2 * ks + ac16;
                    ldsm_x4(af[t],
                            bufu + t * A_TERM_BYTES + arow0 * 128 +
                            ((c16 ^ (arow0 & 7)) << 4));
                }
                {
                    const int c16 = 2 * ks + bc16;
                    ldsm_x4(bf_[t],
                            bufu + B_BASE + t * B_TERM_BYTES + brow0 * 128 +
                            ((c16 ^ (brow0 & 7)) << 4));
                }
            }
            // products with i+j<=1: (0,0), (0,1), (1,0)
            const int pa[3] = {0, 0, 1};
            const int pb[3] = {0, 1, 0};
#pragma unroll
            for (int p = 0; p < 3; p++)
#pragma unroll
                for (int ns = 0; ns < 2; ns++)
                    mma_bf16(acc[ns], af[pa[p]],
                             bf_[pb[p]][ns * 2], bf_[pb[p]][ns * 2 + 1]);
        }
    }
    __syncthreads();   // all compute done before overlaying L/S on buffers

    // ---- epilogue: bias add, logits to gmem + smem ----
    const float* bias_s = (const float*)(sm + OFF_BIAS);
    float* L = (float*)(sm + OFF_L);
    float* S = (float*)(sm + OFF_S);
    {
        const int g = lane >> 2, tg = lane & 3;
#pragma unroll
        for (int ns = 0; ns < 2; ns++) {
            const int col = 16 * ng + 8 * ns + 2 * tg;
            const float bx = bias_s[col], by = bias_s[col + 1];
#pragma unroll
            for (int half = 0; half < 2; half++) {
                const int row = 16 * mg + g + 8 * half;
                float vx = acc[ns][half * 2 + 0] + bx;
                float vy = acc[ns][half * 2 + 1] + by;
                L[row * 64 + col]     = vx;
                L[row * 64 + col + 1] = vy;
                *(float2*)(out_logits + (size_t)(bm + row) * 64 + col) =
                    make_float2(vx, vy);
            }
        }
    }
    __syncthreads();

    // ---- router: softmax + Gumbel top-k; 8 warps x 4 rows ----
    const int kk = kptr ? *kptr : 8;
    const int ln = lane;
    float* vk = (float*)(sm + OFF_VK) + wid * 2;

    for (int rr = 0; rr < 4; rr++) {
        const int r = wid * 4 + rr;
        const int grow = bm + r;
        const float l0 = L[r * 64 + ln];
        const float l1 = L[r * 64 + ln + 32];

        const uint32_t j0 = (uint32_t)(grow * 64 + ln);
        const float g0 = -logf(-logf(bits_to_unif(threefry_bits(j0))));
        const float g1 = -logf(-logf(bits_to_unif(threefry_bits(j0 + 32u))));
        float sc0 = l0 + g0;
        float sc1 = l1 + g1;
        S[r * 64 + ln]      = sc0;
        S[r * 64 + ln + 32] = sc1;
        __syncwarp();

        // softmax weights (from mma logits; error << 1e-3 threshold)
        float m = fmaxf(l0, l1);
#pragma unroll
        for (int d2 = 16; d2 >= 1; d2 >>= 1)
            m = fmaxf(m, __shfl_xor_sync(0xFFFFFFFFu, m, d2));
        const float e0 = expf(l0 - m);
        const float e1 = expf(l1 - m);
        float z = e0 + e1;
#pragma unroll
        for (int d2 = 16; d2 >= 1; d2 >>= 1)
            z += __shfl_xor_sync(0xFFFFFFFFu, z, d2);
        const float w0 = e0 / z;
        const float w1 = e1 / z;

        // top-k rank count; ties -> lower index (lax.top_k stability)
        int c0 = 0, c1 = 0;
#pragma unroll 16
        for (int i = 0; i < 64; i++) {
            const float v = S[r * 64 + i];
            c0 += (v > sc0) || (v == sc0 && i < ln);
            c1 += (v > sc1) || (v == sc1 && i < ln + 32);
        }

        // ---- knife-edge detection: gap between rank kk-1 and rank kk ----
        if (c0 == kk - 1) vk[0] = sc0;
        if (c1 == kk - 1) vk[0] = sc1;
        if (c0 == kk)     vk[1] = sc0;
        if (c1 == kk)     vk[1] = sc1;
        __syncwarp();
        const bool flagged = (vk[0] - vk[1] < GAP_TAU);   // warp-uniform

        if (flagged) {
            // Recompute this row's logits BIT-IDENTICALLY to the verified
            // fp32 kernel: sequential fma over k ascending, single
            // accumulator, then +bias.
            const float* arow = A + (size_t)grow * D_DIM;
            const float* wp0  = Wfull + (size_t)ln * D_DIM;
            const float* wp1  = Wfull + (size_t)(ln + 32) * D_DIM;
            float p0 = 0.f, p1 = 0.f;
            for (int k4 = 0; k4 < D_DIM; k4 += 4) {
                float4 av = *(const float4*)(arow + k4);
                float4 u0 = *(const float4*)(wp0 + k4);
                float4 u1 = *(const float4*)(wp1 + k4);
                p0 = fmaf(av.x, u0.x, p0); p1 = fmaf(av.x, u1.x, p1);
                p0 = fmaf(av.y, u0.y, p0); p1 = fmaf(av.y, u1.y, p1);
                p0 = fmaf(av.z, u0.z, p0); p1 = fmaf(av.z, u1.z, p1);
                p0 = fmaf(av.w, u0.w, p0); p1 = fmaf(av.w, u1.w, p1);
            }
            sc0 = (p0 + bias_s[ln])      + g0;
            sc1 = (p1 + bias_s[ln + 32]) + g1;
            S[r * 64 + ln]      = sc0;
            S[r * 64 + ln + 32] = sc1;
            __syncwarp();
            c0 = 0; c1 = 0;
#pragma unroll 16
            for (int i = 0; i < 64; i++) {
                const float v = S[r * 64 + i];
                c0 += (v > sc0) || (v == sc0 && i < ln);
                c1 += (v > sc1) || (v == sc1 && i < ln + 32);
            }
        }

        out_mask[j0]         = (c0 < kk) ? 1.0f : 0.0f;
        out_mask[j0 + 32u]   = (c1 < kk) ? 1.0f : 0.0f;
        out_weight[j0]       = w0;
        out_weight[j0 + 32u] = w1;
        __syncwarp();
    }
}

// ---------------------------------------------------------------------------
// Output layout: tuple (mask, weight, logits) concatenated as f32.
// ---------------------------------------------------------------------------
extern "C" void kernel_launch(void* const* d_in, const int* in_sizes, int n_in,
                              void* d_out, int out_size) {
    const float* h    = (const float*)d_in[0];
    const float* W    = (const float*)d_in[1];
    const float* bias = (const float*)d_in[2];
    const int*   kptr = (n_in > 3) ? (const int*)d_in[3] : nullptr;

    float* out        = (float*)d_out;
    float* out_mask   = out;
    float* out_weight = out + (size_t)T_DIM * E_DIM;
    float* out_logits = out + 2 * (size_t)T_DIM * E_DIM;

    cudaFuncSetAttribute(router_mma_kernel,
                         cudaFuncAttributeMaxDynamicSharedMemorySize, SMEM_BYTES);
    bsplit_kernel<<<(E_DIM * D_DIM + 255) / 256, 256>>>(W);
    router_mma_kernel<<<T_DIM / BM, NTHREADS, SMEM_BYTES>>>(h, W, bias, kptr,
                                                            out_mask, out_weight,
                                                            out_logits);
}